// round 10
// baseline (speedup 1.0000x reference)
#include <cuda_runtime.h>

#define NN     512
#define LROWS  4
#define NCTA   128
#define NTH    512

// Persistent state (device globals). g_front reset by fin_kernel each run;
// g_rows is counter-guarded (rewritten before readable every run).
__device__ float g_rows[NN * NN];   // row k as published entering step k
__device__ int   g_front;           // rows [0, g_front) are published
__device__ float g_part[NCTA * 4];  // per-CTA partials

static __device__ __forceinline__ float fex2(float x) {
    float y; asm("ex2.approx.f32 %0, %1;" : "=f"(y) : "f"(x)); return y;
}
static __device__ __forceinline__ int ld_rlx_gpu(const int* p) {   // relaxed: NO ordering stall
    int v; asm volatile("ld.relaxed.gpu.b32 %0, [%1];" : "=r"(v) : "l"(p) : "memory"); return v;
}
static __device__ __forceinline__ void fence_acq() {               // acquire side, on detect only
    asm volatile("fence.acq_rel.gpu;" ::: "memory");
}
static __device__ __forceinline__ void st_rel_gpu(int* p, int v) {
    asm volatile("st.release.gpu.b32 [%0], %1;" :: "l"(p), "r"(v) : "memory");
}

// gamma*ln2*log2(1+e) ~= e*(P0 + e*(P1 + e*P2)), endpoint-exact at e=0,1
#define PC0  0.0989386f
#define PC1 (-0.0417585f)
#define PC2  0.0121347f
#define C1   14.4269504088896f   // 1/(gamma*ln2)

__global__ void __launch_bounds__(NTH, 1) fw_kernel(
    const float* __restrict__ soft, const float* __restrict__ orig,
    const float* __restrict__ dist, const float* __restrict__ flow)
{
    __shared__ float4 a_sv[2];            // parity-buffered column-k broadcast
    __shared__ float  r4[16][4];
    __shared__ volatile int sfront;       // t0's mirror of g_front

    const int t    = threadIdx.x;         // column index
    const int cta  = blockIdx.x;
    const int r0   = cta * LROWS;
    const int lane = t & 31;
    const int wid  = t >> 5;

    float wv[LROWS], dv[LROWS];
    float accC = 0.f, accM = 0.f, accE = 0.f;
#pragma unroll
    for (int lr = 0; lr < LROWS; lr++) {
        int r   = r0 + lr;
        float s = soft[r * NN + t];
        float d = dist[r * NN + t];
        float o = orig[r * NN + t];
        dv[lr]  = d;
        wv[lr]  = (r == t) ? 0.f : (d / (s + 1e-4f));
        accC    = fmaf(s, d, accC);
        accM    = fmaf(s, 1.f - o, accM);
        float z = s * (((r == t) ? 1.f : 0.f) - s);
        accE    = fmaf(z, z, accE);
    }

    if (t == 0) sfront = 0;
    // CTA 0 publishes row 0: store -> per-thread fence -> bar -> ONE release.
    if (r0 == 0) {
        g_rows[t] = wv[0];
        __threadfence();
    }
    __syncthreads();
    if (r0 == 0 && t == 0) st_rel_gpu(&g_front, 1);

    int   f0     = 0;      // t0's cached global frontier
    float rkv    = 0.f;
    bool  havepf = false;

    for (int k = 0; k < NN; k++) {
        const int  p     = k & 1;
        const int  lrk   = k - r0;
        const bool own   = ((unsigned)lrk < (unsigned)LROWS);
        const int  kn    = k + 1;
        const int  lrn   = kn - r0;
        const bool own_n = ((unsigned)lrn < (unsigned)LROWS);

        // ── acquire row k ──
        float rk;
        if (own) {
            rk = (lrk == 0) ? wv[0] : (lrk == 1) ? wv[1] : (lrk == 2) ? wv[2] : wv[3];
        } else if (havepf) {
            rk = rkv;                               // prefetch-hidden
        } else {
            // frontier path: t0 spins RELAXED (no ordering stalls), fence on detect
            if (t == 0 && f0 <= k) {
                do { f0 = ld_rlx_gpu(&g_front); } while (f0 <= k);
                fence_acq();                        // synchronizes-with producer release
                sfront = f0;
            }
            while (sfront <= k) {}                  // LDS spin, no L2 traffic
            __threadfence_block();                  // order LDG after sfront read
            rk = __ldcg(&g_rows[k * NN + t]);
        }
        havepf = false;

        if (t == k) a_sv[p] = make_float4(wv[0], wv[1], wv[2], wv[3]);
        __syncthreads();                  // orders a_sv AND last step's stores+fences
        // owner releases row k with ONE gpu release (proven protocol)
        if (own && t == 0) st_rel_gpu(&g_front, k + 1);

        // t0: hidden frontier refresh — RELAXED issue now, consume after compute
        const bool willpoll = (t == 0) && (f0 <= kn + 1) && (kn < NN);
        int fu = 0;
        if (willpoll) fu = ld_rlx_gpu(&g_front);    // no ordering -> no stall

        const float4 av = a_sv[p];
        const float aarr[4] = {av.x, av.y, av.z, av.w};

        // ── softmin update of 4 register-resident elements ──
#pragma unroll
        for (int lr = 0; lr < LROWS; lr++) {
            float pth = aarr[lr] + rk;            // old w[r][k] + old w[k][t]
            float w   = wv[lr];
            float m   = fminf(w, pth);
            float x   = -fabsf(w - pth) * C1;
            float e   = fex2(x);
            float q   = fmaf(PC2, e, PC1);
            q         = fmaf(q, e, PC0);
            wv[lr]    = fmaf(-e, q, m);           // m - gamma*ln2*log2(1+e)
        }

        // ── early publish of row k+1 data if owned (release after next bar) ──
        if (own_n) {
            float v = (lrn == 0) ? wv[0] : (lrn == 1) ? wv[1]
                    : (lrn == 2) ? wv[2] : wv[3];
            g_rows[kn * NN + t] = v;
            __threadfence();
        }

        // t0: consume refresh; fence only when it actually advanced
        if (willpoll && fu > f0) {
            fence_acq();
            f0 = fu;
            sfront = f0;
        }

        // ── depth-1 prefetch of row k+1 when known published ──
        if (!own_n && kn < NN && sfront > kn) {
            __threadfence_block();
            rkv = __ldcg(&g_rows[kn * NN + t]);
            havepf = true;
        }
    }

    // ── epilogue: utility term from shortest paths ──
    float accU = 0.f;
#pragma unroll
    for (int lr = 0; lr < LROWS; lr++) {
        int r    = r0 + lr;
        float d  = dv[lr];
        float fl = flow[r * NN + t];
        float sp = wv[lr];
        float choice = 1.0f / (1.0f + expf(fmaf(0.005f, sp, -0.01f * d)));
        float ds  = fmaf(-0.5f, sp, d);
        float ug  = fl * choice * ds;
        float elu = (ug > 0.f) ? ug : (expf(ug) - 1.0f);
        accU += elu + 1.0f;
    }

    // ── CTA reduction of the four partials ──
#pragma unroll
    for (int o = 16; o > 0; o >>= 1) {
        accC += __shfl_down_sync(0xffffffffu, accC, o);
        accU += __shfl_down_sync(0xffffffffu, accU, o);
        accE += __shfl_down_sync(0xffffffffu, accE, o);
        accM += __shfl_down_sync(0xffffffffu, accM, o);
    }
    if (lane == 0) { r4[wid][0] = accC; r4[wid][1] = accU; r4[wid][2] = accE; r4[wid][3] = accM; }
    __syncthreads();
    if (t < 16) {
        float a = r4[t][0], b = r4[t][1], c = r4[t][2], d = r4[t][3];
#pragma unroll
        for (int o = 8; o > 0; o >>= 1) {
            a += __shfl_down_sync(0xffffu, a, o);
            b += __shfl_down_sync(0xffffu, b, o);
            c += __shfl_down_sync(0xffffu, c, o);
            d += __shfl_down_sync(0xffffu, d, o);
        }
        if (t == 0) {
            g_part[cta * 4 + 0] = a; g_part[cta * 4 + 1] = b;
            g_part[cta * 4 + 2] = c; g_part[cta * 4 + 3] = d;
        }
    }
    // kernel boundary = full fence; fin_kernel is stream-ordered after us
}

// fin: resets g_front and reduces the 128 CTA partials into the final scalar.
__global__ void fin_kernel(const int* __restrict__ ep, float* __restrict__ out)
{
    const int t = threadIdx.x;           // 128 threads
    const int lane = t & 31, wid = t >> 5;
    __shared__ float s4[4][4];

    if (t == 0) g_front = 0;             // clean state for the next graph replay

    float c = g_part[t * 4 + 0], u = g_part[t * 4 + 1];
    float e = g_part[t * 4 + 2], m = g_part[t * 4 + 3];
#pragma unroll
    for (int o = 16; o > 0; o >>= 1) {
        c += __shfl_down_sync(0xffffffffu, c, o);
        u += __shfl_down_sync(0xffffffffu, u, o);
        e += __shfl_down_sync(0xffffffffu, e, o);
        m += __shfl_down_sync(0xffffffffu, m, o);
    }
    if (lane == 0) { s4[wid][0] = c; s4[wid][1] = u; s4[wid][2] = e; s4[wid][3] = m; }
    __syncthreads();
    if (t == 0) {
        float C = s4[0][0] + s4[1][0] + s4[2][0] + s4[3][0];
        float U = s4[0][1] + s4[1][1] + s4[2][1] + s4[3][1];
        float E = s4[0][2] + s4[1][2] + s4[2][2] + s4[3][2];
        float M = s4[0][3] + s4[1][3] + s4[2][3] + s4[3][3];
        int epoch = *ep;
        int idx = (epoch >= 0) + (epoch >= 10) + (epoch >= 50);  // bisect_right
        const float lv[4] = {0.0f, 0.05f, 0.1f, 1.0f};
        out[0] = C + U + lv[idx] * E + 10000.0f * M;
    }
}

// pad kernels: make the per-replay launch sequence 4 long (nop, fw, fin, nop)
// so ncu's "-s 5 -c 1" capture lands on fw_kernel instead of fin_kernel.
__global__ void nop_a_kernel() {}
__global__ void nop_b_kernel() {}

extern "C" void kernel_launch(void* const* d_in, const int* in_sizes, int n_in,
                              void* d_out, int out_size)
{
    (void)in_sizes; (void)n_in; (void)out_size;
    const float* soft = (const float*)d_in[0];
    const float* orig = (const float*)d_in[1];
    const float* dist = (const float*)d_in[2];
    const float* flow = (const float*)d_in[3];
    const int*   ep   = (const int*)d_in[4];

    nop_a_kernel<<<1, 32>>>();
    fw_kernel<<<NCTA, NTH>>>(soft, orig, dist, flow);
    fin_kernel<<<1, NCTA>>>(ep, (float*)d_out);
    nop_b_kernel<<<1, 32>>>();
}

// round 11
// speedup vs baseline: 1.1616x; 1.1616x over previous
#include <cuda_runtime.h>

#define NN     512
#define LROWS  4
#define NCTA   128
#define NTH    512

// Persistent state (device globals). Frontier replicas reset by fin_kernel each
// run; g_rows is counter-guarded (rewritten before readable every run).
__device__ float g_rows[NN * NN];          // row k as published entering step k
__device__ int   g_front_arr[NCTA][32];    // per-CTA frontier replica, one 128B line each
__device__ float g_part[NCTA * 4];         // per-CTA partials

static __device__ __forceinline__ float fex2(float x) {
    float y; asm("ex2.approx.f32 %0, %1;" : "=f"(y) : "f"(x)); return y;
}
static __device__ __forceinline__ int ld_acq_gpu(const int* p) {
    int v; asm volatile("ld.acquire.gpu.b32 %0, [%1];" : "=r"(v) : "l"(p) : "memory"); return v;
}
static __device__ __forceinline__ void st_rel_gpu(int* p, int v) {
    asm volatile("st.release.gpu.b32 [%0], %1;" :: "l"(p), "r"(v) : "memory");
}

// gamma*ln2*log2(1+e) ~= e*(P0 + e*(P1 + e*P2)), endpoint-exact at e=0,1
#define PC0  0.0989386f
#define PC1 (-0.0417585f)
#define PC2  0.0121347f
#define C1   14.4269504088896f   // 1/(gamma*ln2)

__global__ void __launch_bounds__(NTH, 1) fw_kernel(
    const float* __restrict__ soft, const float* __restrict__ orig,
    const float* __restrict__ dist, const float* __restrict__ flow)
{
    __shared__ float4 a_sv[2];            // parity-buffered column-k broadcast
    __shared__ float  r4[16][4];

    const int t    = threadIdx.x;         // column index
    const int cta  = blockIdx.x;
    const int r0   = cta * LROWS;
    const int lane = t & 31;
    const int wid  = t >> 5;
    const int* myfront = &g_front_arr[cta][0];   // this CTA's private frontier word

    float wv[LROWS], dv[LROWS];
    float accC = 0.f, accM = 0.f, accE = 0.f;
#pragma unroll
    for (int lr = 0; lr < LROWS; lr++) {
        int r   = r0 + lr;
        float s = soft[r * NN + t];
        float d = dist[r * NN + t];
        float o = orig[r * NN + t];
        dv[lr]  = d;
        wv[lr]  = (r == t) ? 0.f : (d / (s + 1e-4f));
        accC    = fmaf(s, d, accC);
        accM    = fmaf(s, 1.f - o, accM);
        float z = s * (((r == t) ? 1.f : 0.f) - s);
        accE    = fmaf(z, z, accE);
    }

    // CTA 0 publishes row 0: store -> per-thread fence -> bar -> PARALLEL releases
    // (threads 0..127 each release one replica; each replica on its own line).
    if (r0 == 0) {
        g_rows[t] = wv[0];
        __threadfence();
    }
    __syncthreads();
    if (r0 == 0 && t < NCTA) st_rel_gpu(&g_front_arr[t][0], 1);

    int   fcache = 0;      // this thread's cached view of its CTA's frontier
    float rkv    = 0.f;
    bool  havepf = false;

    for (int k = 0; k < NN; k++) {
        const int  p     = k & 1;
        const int  lrk   = k - r0;
        const bool own   = ((unsigned)lrk < (unsigned)LROWS);
        const int  kn    = k + 1;
        const int  lrn   = kn - r0;
        const bool own_n = ((unsigned)lrn < (unsigned)LROWS);

        // ── acquire row k ──
        float rk;
        if (own) {
            rk = (lrk == 0) ? wv[0] : (lrk == 1) ? wv[1] : (lrk == 2) ? wv[2] : wv[3];
        } else if (havepf) {
            rk = rkv;                               // prefetch-hidden
        } else {
            if (fcache <= k) {
                do { fcache = ld_acq_gpu(myfront); } while (fcache <= k);
            }
            rk = __ldcg(&g_rows[k * NN + t]);       // private line poll -> fast detect
        }
        havepf = false;

        if (t == k) a_sv[p] = make_float4(wv[0], wv[1], wv[2], wv[3]);
        __syncthreads();                  // orders a_sv AND last step's stores+fences
        // owner: 128 threads release 128 replicas IN PARALLEL (proven fence
        // protocol: data stores + per-thread __threadfence happened before bar)
        if (own && t < NCTA) st_rel_gpu(&g_front_arr[t][0], k + 1);

        // frontier probe for prefetch — issued here so the FMA/MUFU block below
        // hides its round trip (compute is register-only; acquire only orders mem ops)
        const bool needp = (!own_n) && (kn < NN) && (fcache <= kn);
        int fp = 0;
        if (needp) fp = ld_acq_gpu(myfront);

        const float4 av = a_sv[p];
        const float aarr[4] = {av.x, av.y, av.z, av.w};

        // ── softmin update of 4 register-resident elements ──
#pragma unroll
        for (int lr = 0; lr < LROWS; lr++) {
            float pth = aarr[lr] + rk;            // old w[r][k] + old w[k][t]
            float w   = wv[lr];
            float m   = fminf(w, pth);
            float x   = -fabsf(w - pth) * C1;
            float e   = fex2(x);
            float q   = fmaf(PC2, e, PC1);
            q         = fmaf(q, e, PC0);
            wv[lr]    = fmaf(-e, q, m);           // m - gamma*ln2*log2(1+e)
        }

        // ── early publish of row k+1 data if owned (release after next bar) ──
        if (own_n) {
            float v = (lrn == 0) ? wv[0] : (lrn == 1) ? wv[1]
                    : (lrn == 2) ? wv[2] : wv[3];
            g_rows[kn * NN + t] = v;
            __threadfence();
        }

        if (needp && fp > fcache) fcache = fp;

        // ── depth-1 prefetch of row k+1 when known published ──
        if (!own_n && kn < NN && fcache > kn) {
            rkv = __ldcg(&g_rows[kn * NN + t]);
            havepf = true;
        }
    }

    // ── epilogue: utility term from shortest paths ──
    float accU = 0.f;
#pragma unroll
    for (int lr = 0; lr < LROWS; lr++) {
        int r    = r0 + lr;
        float d  = dv[lr];
        float fl = flow[r * NN + t];
        float sp = wv[lr];
        float choice = 1.0f / (1.0f + expf(fmaf(0.005f, sp, -0.01f * d)));
        float ds  = fmaf(-0.5f, sp, d);
        float ug  = fl * choice * ds;
        float elu = (ug > 0.f) ? ug : (expf(ug) - 1.0f);
        accU += elu + 1.0f;
    }

    // ── CTA reduction of the four partials ──
#pragma unroll
    for (int o = 16; o > 0; o >>= 1) {
        accC += __shfl_down_sync(0xffffffffu, accC, o);
        accU += __shfl_down_sync(0xffffffffu, accU, o);
        accE += __shfl_down_sync(0xffffffffu, accE, o);
        accM += __shfl_down_sync(0xffffffffu, accM, o);
    }
    if (lane == 0) { r4[wid][0] = accC; r4[wid][1] = accU; r4[wid][2] = accE; r4[wid][3] = accM; }
    __syncthreads();
    if (t < 16) {
        float a = r4[t][0], b = r4[t][1], c = r4[t][2], d = r4[t][3];
#pragma unroll
        for (int o = 8; o > 0; o >>= 1) {
            a += __shfl_down_sync(0xffffu, a, o);
            b += __shfl_down_sync(0xffffu, b, o);
            c += __shfl_down_sync(0xffffu, c, o);
            d += __shfl_down_sync(0xffffu, d, o);
        }
        if (t == 0) {
            g_part[cta * 4 + 0] = a; g_part[cta * 4 + 1] = b;
            g_part[cta * 4 + 2] = c; g_part[cta * 4 + 3] = d;
        }
    }
    // kernel boundary = full fence; fin_kernel is stream-ordered after us
}

// fin: resets all frontier replicas and reduces the 128 CTA partials.
__global__ void fin_kernel(const int* __restrict__ ep, float* __restrict__ out)
{
    const int t = threadIdx.x;           // 128 threads
    const int lane = t & 31, wid = t >> 5;
    __shared__ float s4[4][4];

    g_front_arr[t][0] = 0;               // clean state for the next graph replay

    float c = g_part[t * 4 + 0], u = g_part[t * 4 + 1];
    float e = g_part[t * 4 + 2], m = g_part[t * 4 + 3];
#pragma unroll
    for (int o = 16; o > 0; o >>= 1) {
        c += __shfl_down_sync(0xffffffffu, c, o);
        u += __shfl_down_sync(0xffffffffu, u, o);
        e += __shfl_down_sync(0xffffffffu, e, o);
        m += __shfl_down_sync(0xffffffffu, m, o);
    }
    if (lane == 0) { s4[wid][0] = c; s4[wid][1] = u; s4[wid][2] = e; s4[wid][3] = m; }
    __syncthreads();
    if (t == 0) {
        float C = s4[0][0] + s4[1][0] + s4[2][0] + s4[3][0];
        float U = s4[0][1] + s4[1][1] + s4[2][1] + s4[3][1];
        float E = s4[0][2] + s4[1][2] + s4[2][2] + s4[3][2];
        float M = s4[0][3] + s4[1][3] + s4[2][3] + s4[3][3];
        int epoch = *ep;
        int idx = (epoch >= 0) + (epoch >= 10) + (epoch >= 50);  // bisect_right
        const float lv[4] = {0.0f, 0.05f, 0.1f, 1.0f};
        out[0] = C + U + lv[idx] * E + 10000.0f * M;
    }
}

// Pad kernels: observed capture = my launch index 3 (0-based). Put fw there so
// ncu finally profiles the main kernel. (~10us timing cost, one round only.)
__global__ void nop_a_kernel() {}
__global__ void nop_b_kernel() {}
__global__ void nop_c_kernel() {}

extern "C" void kernel_launch(void* const* d_in, const int* in_sizes, int n_in,
                              void* d_out, int out_size)
{
    (void)in_sizes; (void)n_in; (void)out_size;
    const float* soft = (const float*)d_in[0];
    const float* orig = (const float*)d_in[1];
    const float* dist = (const float*)d_in[2];
    const float* flow = (const float*)d_in[3];
    const int*   ep   = (const int*)d_in[4];

    nop_a_kernel<<<1, 32>>>();
    nop_b_kernel<<<1, 32>>>();
    nop_c_kernel<<<1, 32>>>();
    fw_kernel<<<NCTA, NTH>>>(soft, orig, dist, flow);   // index 3 -> ncu target
    fin_kernel<<<1, NCTA>>>(ep, (float*)d_out);
}